// round 8
// baseline (speedup 1.0000x reference)
#include <cuda_runtime.h>

#define NN      512
#define TILE    32
#define TG      (NN / TILE)
#define BIGV    1e10f
#define SRC_I   256
#define SRC_J   256
#define PASSES  16
#define SU_S    36
#define WBUF    (TILE * TILE + 1)

__device__ float g_u2[NN * NN];

__device__ __forceinline__ int suidx(int i, int j) { return (i + 1) * SU_S + (j + 1); }

__global__ void eik_init(float* __restrict__ u) {
    int idx = blockIdx.x * blockDim.x + threadIdx.x;
    if (idx < NN * NN) u[idx] = (idx == SRC_I * NN + SRC_J) ? 0.0f : BIGV;
}

// raw shuffles: exactly one SHFL each in SASS, no compiler WARPSYNC
__device__ __forceinline__ float shup1(float v) {
    float r;
    asm("shfl.sync.up.b32 %0, %1, 1, 0x0, 0xffffffff;" : "=f"(r) : "f"(v));
    return r;
}
__device__ __forceinline__ float shdn1(float v) {
    float r;
    asm("shfl.sync.down.b32 %0, %1, 1, 0x1f, 0xffffffff;" : "=f"(r) : "f"(v));
    return r;
}

// State + one wavefront step of a single directional GS sweep (R6 semantics).
template <int DI, int DJ>
struct Dir {
    const float*  su_in;
    const float2* sf2;
    float*        su_w;
    int   j, i0;
    float uprev, o_cur, o_nxt, hl, hr;
    float2 fv;

    __device__ __forceinline__ void init(const float* su, const float2* sf,
                                         float* sw, int t) {
        su_in = su; sf2 = sf; su_w = sw;
        j  = (DJ > 0) ? t : (TILE - 1 - t);
        i0 = (DI > 0) ? 0 : (TILE - 1);
        const int jlH = (DJ > 0) ? -1 : TILE;
        const int jrH = (DJ > 0) ? TILE : -1;
        uprev = su_in[suidx(i0 - DI, j)];
        o_cur = su_in[suidx(i0, j)];
        int r1 = (1 - t) > 0 ? (1 - t) : 0;
        o_nxt = su_in[suidx(i0 + DI * r1, j)];
        fv    = sf2[i0 * TILE + j];
        hl    = su_in[suidx(i0, jlH)];
        hr    = su_in[suidx(i0, jrH)];
    }

    __device__ __forceinline__ void step(bool active, int iic, int rn, int rf,
                                         int sh, int sr, bool e0, bool e31) {
        const int i   = i0 + DI * iic;
        const int jlH = (DJ > 0) ? -1 : TILE;
        const int jrH = (DJ > 0) ? TILE : -1;

        const float lup = shup1(uprev);
        const float rdn = shdn1(o_nxt);
        const float lft = e0  ? hl : lup;
        const float rt  = e31 ? hr : rdn;

        const float a   = fminf(uprev, o_nxt);
        const float b   = fminf(lft, rt);
        const float mn  = fminf(a, b);
        const float d   = fabsf(a - b);
        const float hab = 0.5f * (a + b);
        const float arg = fmaxf(fmaf(-d, d, fv.y), 0.0f);
        float rq;
        asm("sqrt.approx.f32 %0, %1;" : "=f"(rq) : "f"(arg));
        const float cand = (d >= fv.x) ? (mn + fv.x) : fmaf(0.5f, rq, hab);
        const float nu   = fminf(o_cur, cand);

        su_w[active ? (i * TILE + j) : (TILE * TILE)] = nu;
        uprev = active ? nu : uprev;

        // roll + prefetch (clamped reads only over-estimate -> monotone-safe)
        o_cur = o_nxt;
        o_nxt = su_in[suidx(i0 + DI * rn, j)];
        fv    = sf2[(i0 + DI * rf) * TILE + j];
        hl    = su_in[suidx(i0 + DI * sh, jlH)];
        hr    = su_in[suidx(i0 + DI * sr, jrH)];
    }
};

// Two opposite directions interleaved in one warp: independent chains give the
// in-order core ILP to hide per-instruction producer waits.
template <int DI, int DJ>
__device__ __forceinline__ void sweep_pair(const float* su_in, const float2* sf2,
                                           float* swA, float* swB, int t) {
    Dir<DI, DJ>   A;
    Dir<-DI, -DJ> B;
    A.init(su_in, sf2, swA, t);
    B.init(su_in, sf2, swB, t);
    const bool e0  = (t == 0);
    const bool e31 = (t == TILE - 1);

#pragma unroll 1
    for (int s = 0; s < 2 * TILE - 1; ++s) {
        const int  ii     = s - t;
        const bool active = ((unsigned)ii < (unsigned)TILE);
        const int  iic    = active ? ii : 0;
        // shared clamped indices (identical for both directions)
        int rn = ii + 2; rn = rn < 0 ? 0 : (rn > 31 ? 31 : rn);
        int rf = ii + 1; rf = rf < 0 ? 0 : (rf > 31 ? 31 : rf);
        int sh = s + 1;  sh = sh > 31 ? 31 : sh;
        int sr = s - 30; sr = sr < 0 ? 0 : (sr > 31 ? 31 : sr);

        A.step(active, iic, rn, rf, sh, sr, e0, e31);
        B.step(active, iic, rn, rf, sh, sr, e0, e31);
    }
}

__global__ __launch_bounds__(64) void eik_sweep(const float* __restrict__ src,
                                                float* __restrict__ dst,
                                                const float* __restrict__ f) {
    __shared__ float  su_in[(TILE + 2) * SU_S];
    __shared__ float2 sf2  [TILE * TILE];
    __shared__ float  su_w [4][WBUF];

    const int tid = threadIdx.x;
    const int w   = tid >> 5;
    const int t   = tid & 31;
    const int gi0 = blockIdx.y * TILE, gj0 = blockIdx.x * TILE;

    // 34x34 u tile (+halo), BIG outside domain
#pragma unroll 1
    for (int idx = tid; idx < (TILE + 2) * (TILE + 2); idx += 64) {
        const int rr = idx / (TILE + 2);
        const int cc = idx - rr * (TILE + 2);
        const int gi = gi0 - 1 + rr;
        const int gj = gj0 - 1 + cc;
        const bool in = (gi >= 0) && (gi < NN) && (gj >= 0) && (gj < NN);
        su_in[rr * SU_S + cc] = in ? src[gi * NN + gj] : BIGV;
    }
#pragma unroll 1
    for (int idx = tid; idx < TILE * TILE; idx += 64) {
        const int r = idx >> 5, c = idx & 31;
        const float fh = f[(gi0 + r) * NN + gj0 + c];
        sf2[idx] = make_float2(fh, 2.0f * fh * fh);
    }
    __syncthreads();

    if (w == 0) sweep_pair<1,  1>(su_in, sf2, su_w[0], su_w[1], t);
    else        sweep_pair<1, -1>(su_in, sf2, su_w[2], su_w[3], t);
    __syncthreads();

    // 4-way min merge -> dst
#pragma unroll 1
    for (int idx = tid; idx < TILE * TILE; idx += 64) {
        const float v = fminf(fminf(su_w[0][idx], su_w[1][idx]),
                              fminf(su_w[2][idx], su_w[3][idx]));
        const int r = idx >> 5, c = idx & 31;
        dst[(gi0 + r) * NN + gj0 + c] = v;
    }
}

extern "C" void kernel_launch(void* const* d_in, const int* in_sizes, int n_in,
                              void* d_out, int out_size) {
    const float* f = (const float*)d_in[0];
    float* u = (float*)d_out;

    void* p2 = nullptr;
    cudaGetSymbolAddress(&p2, g_u2);
    float* u2 = (float*)p2;

    eik_init<<<(NN * NN + 255) / 256, 256>>>(u);

    dim3 grid(TG, TG);
    for (int p = 0; p < PASSES; ++p) {
        if ((p & 1) == 0) eik_sweep<<<grid, 64>>>(u,  u2, f);
        else              eik_sweep<<<grid, 64>>>(u2, u,  f);
    }
}

// round 9
// speedup vs baseline: 1.6207x; 1.6207x over previous
#include <cuda_runtime.h>

#define NN      512
#define TILE    32
#define TG      (NN / TILE)
#define BIGV    1e10f
#define SRC_I   256
#define SRC_J   256
#define PASSES  16              // includes the fused INIT pass
#define SU_S    36
#define WBUF    (TILE * TILE + 1)

__device__ float g_u2[NN * NN];

__device__ __forceinline__ int suidx(int i, int j) { return (i + 1) * SU_S + (j + 1); }

// raw shuffles: exactly one SHFL in SASS, no compiler-inserted WARPSYNC
__device__ __forceinline__ float shup1(float v) {
    float r;
    asm("shfl.sync.up.b32 %0, %1, 1, 0x0, 0xffffffff;" : "=f"(r) : "f"(v));
    return r;
}
__device__ __forceinline__ float shdn1(float v) {
    float r;
    asm("shfl.sync.down.b32 %0, %1, 1, 0x1f, 0xffffffff;" : "=f"(r) : "f"(v));
    return r;
}

// One directional GS wavefront over an immutable input tile (R6 engine).
// Lane t owns physical col j; step s handles sweep-row ii = s - t. Branch-free;
// results to this warp's private buffer via plain STS (idle lanes -> dump slot).
template <int DI, int DJ>
__device__ __forceinline__ void sweep_dir(const float* __restrict__ su_in,
                                          float*       __restrict__ su_w,
                                          const float2* __restrict__ sf2,
                                          int t) {
    const int j   = (DJ > 0) ? t : (TILE - 1 - t);
    const int jlH = (DJ > 0) ? -1   : TILE;
    const int jrH = (DJ > 0) ? TILE : -1;
    const int i0  = (DI > 0) ? 0 : (TILE - 1);
    const bool e0  = (t == 0);
    const bool e31 = (t == TILE - 1);

    float uprev = su_in[suidx(i0 - DI, j)];
    float o_cur = su_in[suidx(i0, j)];
    int   r1    = (1 - t) > 0 ? (1 - t) : 0;
    float o_nxt = su_in[suidx(i0 + DI * r1, j)];
    float2 fv   = sf2[i0 * TILE + j];
    float  hl   = su_in[suidx(i0, jlH)];
    float  hr   = su_in[suidx(i0, jrH)];

#pragma unroll 1
    for (int s = 0; s < 2 * TILE - 1; ++s) {
        const int  ii     = s - t;
        const bool active = ((unsigned)ii < (unsigned)TILE);
        const int  iic    = active ? ii : 0;
        const int  i      = i0 + DI * iic;

        const float lup = shup1(uprev);
        const float rdn = shdn1(o_nxt);
        const float lft = e0  ? hl : lup;
        const float rt  = e31 ? hr : rdn;

        const float a   = fminf(uprev, o_nxt);
        const float b   = fminf(lft,   rt);
        const float mn  = fminf(a, b);
        const float d   = fabsf(a - b);
        const float hab = 0.5f * (a + b);

        const float arg = fmaxf(fmaf(-d, d, fv.y), 0.0f);
        float rq;
        asm("sqrt.approx.f32 %0, %1;" : "=f"(rq) : "f"(arg));

        const float cand = (d >= fv.x) ? (mn + fv.x) : fmaf(0.5f, rq, hab);
        const float nu   = fminf(o_cur, cand);

        su_w[active ? (i * TILE + j) : (TILE * TILE)] = nu;
        uprev = active ? nu : uprev;

        // roll windows + prefetch (clamped reads only over-estimate -> safe)
        o_cur = o_nxt;
        int rn = ii + 2; rn = rn < 0 ? 0 : (rn > 31 ? 31 : rn);
        o_nxt = su_in[suidx(i0 + DI * rn, j)];
        int rf = ii + 1; rf = rf < 0 ? 0 : (rf > 31 ? 31 : rf);
        fv = sf2[(i0 + DI * rf) * TILE + j];
        int sh = s + 1;  sh = sh > 31 ? 31 : sh;
        hl = su_in[suidx(i0 + DI * sh, jlH)];
        int sr = s - 30; sr = sr < 0 ? 0 : (sr > 31 ? 31 : sr);
        hr = su_in[suidx(i0 + DI * sr, jrH)];
    }
}

template <bool INIT>
__global__ __launch_bounds__(128) void eik_sweep(const float* __restrict__ src,
                                                 float* __restrict__ dst,
                                                 const float* __restrict__ f) {
    __shared__ float  su_in[(TILE + 2) * SU_S];
    __shared__ float2 sf2  [TILE * TILE];
    __shared__ float  su_w [4][WBUF];

    const int tid = threadIdx.x;
    const int w   = tid >> 5;
    const int t   = tid & 31;
    const int gi0 = blockIdx.y * TILE, gj0 = blockIdx.x * TILE;

    // 34x34 u tile (+halo). INIT pass synthesizes u = BIG (+source=0): no loads.
#pragma unroll 1
    for (int idx = tid; idx < (TILE + 2) * (TILE + 2); idx += 128) {
        const int rr = idx / (TILE + 2);
        const int cc = idx - rr * (TILE + 2);
        const int gi = gi0 - 1 + rr;
        const int gj = gj0 - 1 + cc;
        float v;
        if (INIT) {
            v = (gi == SRC_I && gj == SRC_J) ? 0.0f : BIGV;
        } else {
            const bool in = (gi >= 0) && (gi < NN) && (gj >= 0) && (gj < NN);
            v = in ? src[gi * NN + gj] : BIGV;
        }
        su_in[rr * SU_S + cc] = v;
    }
#pragma unroll 1
    for (int idx = tid; idx < TILE * TILE; idx += 128) {
        const int r = idx >> 5, c = idx & 31;
        const float fh = f[(gi0 + r) * NN + gj0 + c];
        sf2[idx] = make_float2(fh, 2.0f * fh * fh);
    }
    __syncthreads();

    if      (w == 0) sweep_dir< 1,  1>(su_in, su_w[0], sf2, t);
    else if (w == 1) sweep_dir< 1, -1>(su_in, su_w[1], sf2, t);
    else if (w == 2) sweep_dir<-1,  1>(su_in, su_w[2], sf2, t);
    else             sweep_dir<-1, -1>(su_in, su_w[3], sf2, t);
    __syncthreads();

    // 4-way min merge -> dst (each nu already includes min with old value)
#pragma unroll 1
    for (int idx = tid; idx < TILE * TILE; idx += 128) {
        const float v = fminf(fminf(su_w[0][idx], su_w[1][idx]),
                              fminf(su_w[2][idx], su_w[3][idx]));
        const int r = idx >> 5, c = idx & 31;
        dst[(gi0 + r) * NN + gj0 + c] = v;
    }
}

extern "C" void kernel_launch(void* const* d_in, const int* in_sizes, int n_in,
                              void* d_out, int out_size) {
    const float* f = (const float*)d_in[0];
    float* u = (float*)d_out;

    void* p2 = nullptr;
    cudaGetSymbolAddress(&p2, g_u2);
    float* u2 = (float*)p2;

    dim3 grid(TG, TG);
    // p0 (INIT) -> u2 ; p1 -> u ; ... ; p15 -> u == d_out
    eik_sweep<true><<<grid, 128>>>(u, u2, f);
    for (int p = 1; p < PASSES; ++p) {
        if (p & 1) eik_sweep<false><<<grid, 128>>>(u2, u,  f);
        else       eik_sweep<false><<<grid, 128>>>(u,  u2, f);
    }
}